// round 3
// baseline (speedup 1.0000x reference)
#include <cuda_runtime.h>
#include <cstdint>

#define NN 50000
#define NE 800000
#define SD 128
#define NG 128
#define NC 41
#define BN_EPS 1e-5f

// ---------------- scratch (static device globals; no runtime alloc) -------
__device__ float g_x[NN * SD];
__device__ float g_y[NN * SD];
__device__ float g_h[NN * SD];
__device__ int   g_deg[NN];
__device__ int   g_rowptr[NN + 1];
__device__ int   g_cursor[NN];
__device__ int   g_csrsrc[NE];
__device__ float g_pool[NG * SD];

// ---------------- small utility kernels ----------------------------------
__global__ void k_zero_deg() {
    int i = blockIdx.x * blockDim.x + threadIdx.x;
    if (i < NN) g_deg[i] = 0;
}
__global__ void k_zero_pool() {
    int i = blockIdx.x * blockDim.x + threadIdx.x;
    if (i < NG * SD) g_pool[i] = 0.f;
}
__global__ void k_hist(const int* __restrict__ dst) {
    int e = blockIdx.x * blockDim.x + threadIdx.x;
    if (e < NE) atomicAdd(&g_deg[dst[e]], 1);
}
__global__ void k_scan() {
    __shared__ int wsum[32];
    int tid = threadIdx.x, lane = tid & 31, wid = tid >> 5;
    int base = 0;
    for (int c0 = 0; c0 < NN; c0 += 1024) {
        int i = c0 + tid;
        int v = (i < NN) ? g_deg[i] : 0;
        int s = v;
#pragma unroll
        for (int d = 1; d < 32; d <<= 1) {
            int t = __shfl_up_sync(0xffffffffu, s, d);
            if (lane >= d) s += t;
        }
        if (lane == 31) wsum[wid] = s;
        __syncthreads();
        if (wid == 0) {
            int t = wsum[lane];
#pragma unroll
            for (int d = 1; d < 32; d <<= 1) {
                int u = __shfl_up_sync(0xffffffffu, t, d);
                if (lane >= d) t += u;
            }
            wsum[lane] = t;
        }
        __syncthreads();
        int off = base + (wid ? wsum[wid - 1] : 0) + s - v;
        if (i < NN) { g_rowptr[i] = off; g_cursor[i] = off; }
        base += wsum[31];
        __syncthreads();
    }
    if (tid == 0) g_rowptr[NN] = base;
}
__global__ void k_csr(const int* __restrict__ src, const int* __restrict__ dst) {
    int e = blockIdx.x * blockDim.x + threadIdx.x;
    if (e < NE) {
        int p = atomicAdd(&g_cursor[dst[e]], 1);
        g_csrsrc[p] = src[e];
    }
}
__global__ void k_embed(const int* __restrict__ ids, const float* __restrict__ emb) {
    int t = blockIdx.x * blockDim.x + threadIdx.x;
    if (t >= NN * 32) return;
    int n = t >> 5, q = t & 31;
    ((float4*)g_x)[n * 32 + q] = ((const float4*)emb)[(long)ids[n] * 32 + q];
}

// warp-per-node: y[i] = x[i] + sum_{j in N(i)} x[j]
__global__ void k_agg() {
    int w = (blockIdx.x * blockDim.x + threadIdx.x) >> 5;
    int lane = threadIdx.x & 31;
    if (w >= NN) return;
    const float4* x4 = (const float4*)g_x;
    float4 a = x4[w * 32 + lane];
    int e = g_rowptr[w], end = g_rowptr[w + 1];
    for (; e + 2 <= end; e += 2) {
        int j0 = g_csrsrc[e], j1 = g_csrsrc[e + 1];
        float4 v0 = x4[j0 * 32 + lane];
        float4 v1 = x4[j1 * 32 + lane];
        a.x += v0.x + v1.x; a.y += v0.y + v1.y;
        a.z += v0.z + v1.z; a.w += v0.w + v1.w;
    }
    if (e < end) {
        int j = g_csrsrc[e];
        float4 v = x4[j * 32 + lane];
        a.x += v.x; a.y += v.y; a.z += v.z; a.w += v.w;
    }
    ((float4*)g_y)[w * 32 + lane] = a;
}

// ---------------- tensor-core GEMM via mma.sync (3xTF32 split) -------------
// C[i][j] = epi( sum_k A[i][k]*W[j][k] + b[j] );  CTA tile M=128, N=128, K=128.
// SMEM fragment-permuted storage:
//  W (hi/lo): [gk 0..15][nt 0..15][lane][2]  (float2 per lane -> b0,b1)
//  A (hi/lo): [ks 0..7 ][mt 0..7 ][lane][4]  (float4 per lane -> a0..a3), K chunked by 64
#define W_FLOATS (16 * 16 * 32 * 2)   // 16384 floats = 64KB
#define A_FLOATS (8 * 8 * 32 * 4)     // 8192 floats  = 32KB
#define SM_FLOATS (2 * W_FLOATS + 2 * A_FLOATS)   // 49152 floats = 192KB
#define SM_REQ (SM_FLOATS * 4)

__device__ __forceinline__ float tf32_trunc(float v) {
    return __uint_as_float(__float_as_uint(v) & 0xffffe000u);
}

__device__ __forceinline__ void mma1688(float* c, const float4& a, const float2& b) {
    const uint32_t* A = reinterpret_cast<const uint32_t*>(&a);
    const uint32_t* B = reinterpret_cast<const uint32_t*>(&b);
    asm volatile(
        "mma.sync.aligned.m16n8k8.row.col.f32.tf32.tf32.f32 "
        "{%0,%1,%2,%3}, {%4,%5,%6,%7}, {%8,%9}, {%0,%1,%2,%3};"
        : "+f"(c[0]), "+f"(c[1]), "+f"(c[2]), "+f"(c[3])
        : "r"(A[0]), "r"(A[1]), "r"(A[2]), "r"(A[3]), "r"(B[0]), "r"(B[1]));
}

template <int BN_MODE>
__global__ void __launch_bounds__(256, 1) k_gemm_tc(
    const float* __restrict__ A, const float* __restrict__ W,
    const float* __restrict__ bias,
    const float* __restrict__ gamma, const float* __restrict__ beta,
    const float* __restrict__ mean, const float* __restrict__ var,
    float* __restrict__ C)
{
    extern __shared__ float s[];
    float* sWhi = s;
    float* sWlo = s + W_FLOATS;
    float* sAhi = s + 2 * W_FLOATS;
    float* sAlo = s + 2 * W_FLOATS + A_FLOATS;

    const int tid  = threadIdx.x;
    const int lane = tid & 31;
    const int wid  = tid >> 5;
    const int r0   = blockIdx.x * 128;
    const int wm   = (wid & 3) * 32;   // warp row offset  (0,32,64,96)
    const int wn   = (wid >> 2) * 64;  // warp col offset  (0,64)

    // ---- stage W (split + permute). thread t: n = t/2, k half = (t&1)*64 ----
    {
        int n = tid >> 1;
        int kh = (tid & 1) * 64;
        const float4* wrow = (const float4*)(W + (long)n * 128 + kh);
#pragma unroll
        for (int q = 0; q < 16; q++) {
            float4 v = wrow[q];
#pragma unroll
            for (int j = 0; j < 4; j++) {
                int k = kh + q * 4 + j;
                float val = (&v.x)[j];
                float hi = tf32_trunc(val);
                float lo = tf32_trunc(val - hi);
                int idx = (((k >> 3) * 16 + (n >> 3)) * 32 + ((n & 7) * 4 + (k & 3))) * 2 + ((k & 7) >> 2);
                sWhi[idx] = hi;
                sWlo[idx] = lo;
            }
        }
    }

    float acc[2][8][4];
#pragma unroll
    for (int m = 0; m < 2; m++)
#pragma unroll
        for (int n = 0; n < 8; n++)
#pragma unroll
            for (int j = 0; j < 4; j++) acc[m][n][j] = 0.f;

    for (int c = 0; c < 2; c++) {
        __syncthreads();
        // ---- stage A chunk (rows r0..r0+127, k in [c*64, c*64+64)) ----
        {
            int row = tid >> 1;
            int kq = (tid & 1) * 32;       // local k within chunk: kq..kq+31
            int gr = r0 + row;
            const float4* arow = (const float4*)(A + (long)gr * 128 + c * 64 + kq);
#pragma unroll
            for (int q = 0; q < 8; q++) {
                float4 v = make_float4(0.f, 0.f, 0.f, 0.f);
                if (gr < NN) v = arow[q];
#pragma unroll
                for (int j = 0; j < 4; j++) {
                    int k = kq + q * 4 + j;   // 0..63 local
                    float val = (&v.x)[j];
                    float hi = tf32_trunc(val);
                    float lo = tf32_trunc(val - hi);
                    int idx = (((k >> 3) * 8 + (row >> 4)) * 32 + (((row & 15) & 7) * 4 + (k & 3))) * 4
                              + (((k & 7) >> 2) << 1) + ((row & 15) >> 3);
                    sAhi[idx] = hi;
                    sAlo[idx] = lo;
                }
            }
        }
        __syncthreads();

        // ---- compute: 8 k-steps, 2 m-tiles x 8 n-tiles x 3 passes ----
#pragma unroll
        for (int ks = 0; ks < 8; ks++) {
            float4 ah[2], al[2];
#pragma unroll
            for (int m = 0; m < 2; m++) {
                int mt = (wm >> 4) + m;
                int ai = ((ks * 8 + mt) * 32 + lane) * 4;
                ah[m] = *(const float4*)(sAhi + ai);
                al[m] = *(const float4*)(sAlo + ai);
            }
            int gk = c * 8 + ks;
#pragma unroll
            for (int n = 0; n < 8; n++) {
                int nt = (wn >> 3) + n;
                int wi = ((gk * 16 + nt) * 32 + lane) * 2;
                float2 wh = *(const float2*)(sWhi + wi);
                float2 wl = *(const float2*)(sWlo + wi);
#pragma unroll
                for (int m = 0; m < 2; m++) {
                    mma1688(acc[m][n], ah[m], wh);
                    mma1688(acc[m][n], ah[m], wl);
                    mma1688(acc[m][n], al[m], wh);
                }
            }
        }
    }

    // ---- epilogue: bias/relu/(bn), store float2 per c-pair ----
#pragma unroll
    for (int m = 0; m < 2; m++) {
        int rbase = r0 + wm + m * 16 + (lane >> 2);
#pragma unroll
        for (int n = 0; n < 8; n++) {
            int col = wn + n * 8 + (lane & 3) * 2;
            float b0 = __ldg(&bias[col]), b1 = __ldg(&bias[col + 1]);
            float sc0 = 0.f, sc1 = 0.f, mn0 = 0.f, mn1 = 0.f, bt0 = 0.f, bt1 = 0.f;
            if (BN_MODE) {
                sc0 = __ldg(&gamma[col]) * rsqrtf(__ldg(&var[col]) + BN_EPS);
                sc1 = __ldg(&gamma[col + 1]) * rsqrtf(__ldg(&var[col + 1]) + BN_EPS);
                mn0 = __ldg(&mean[col]); mn1 = __ldg(&mean[col + 1]);
                bt0 = __ldg(&beta[col]); bt1 = __ldg(&beta[col + 1]);
            }
#pragma unroll
            for (int h = 0; h < 2; h++) {     // h=0: rows, h=1: rows+8
                int r = rbase + h * 8;
                if (r < NN) {
                    float z0 = fmaxf(acc[m][n][h * 2 + 0] + b0, 0.f);
                    float z1 = fmaxf(acc[m][n][h * 2 + 1] + b1, 0.f);
                    if (BN_MODE) {
                        z0 = (z0 - mn0) * sc0 + bt0;
                        z1 = (z1 - mn1) * sc1 + bt1;
                    }
                    *(float2*)(C + (long)r * 128 + col) = make_float2(z0, z1);
                }
            }
        }
    }
}

// ---------------- pooling (batch is sorted -> run-length accumulate) ------
#define NODES_PB 250
__global__ void k_pool(const int* __restrict__ batch) {
    int c = threadIdx.x;
    int n0 = blockIdx.x * NODES_PB;
    int n1 = n0 + NODES_PB;
    if (n1 > NN) n1 = NN;
    if (n0 >= NN) return;
    float acc = 0.f;
    int cur = batch[n0];
    for (int n = n0; n < n1; n++) {
        int b = __ldg(&batch[n]);
        float v = g_x[(long)n * SD + c];
        if (b != cur) {
            atomicAdd(&g_pool[cur * SD + c], acc);
            acc = 0.f; cur = b;
        }
        acc += v;
    }
    atomicAdd(&g_pool[cur * SD + c], acc);
}

// ---------------- tiny FC head: one block per graph -----------------------
__global__ void k_fc(const float* __restrict__ fc1W, const float* __restrict__ fc1b,
                     const float* __restrict__ fc2W, const float* __restrict__ fc2b,
                     float* __restrict__ out) {
    __shared__ float p[SD];
    __shared__ float h[SD];
    int g = blockIdx.x, t = threadIdx.x;
    p[t] = g_pool[g * SD + t];
    __syncthreads();
    float s = fc1b[t];
#pragma unroll 8
    for (int k = 0; k < SD; k++) s += p[k] * fc1W[t * SD + k];
    h[t] = fmaxf(s, 0.f);
    __syncthreads();
    if (t < NC) {
        float s2 = fc2b[t];
#pragma unroll 8
        for (int k = 0; k < SD; k++) s2 += h[k] * fc2W[t * SD + k];
        out[g * NC + t] = s2;
    }
}

// ---------------- launch ---------------------------------------------------
extern "C" void kernel_launch(void* const* d_in, const int* in_sizes, int n_in,
                              void* d_out, int out_size) {
    const int*   node_ids = (const int*)d_in[0];
    const int*   edge     = (const int*)d_in[1];
    const int*   batch    = (const int*)d_in[2];
    const float* emb      = (const float*)d_in[3];
    const float* in_W1    = (const float*)d_in[4];
    const float* in_b1    = (const float*)d_in[5];
    const float* in_W2    = (const float*)d_in[6];
    const float* in_b2    = (const float*)d_in[7];
    const float* bn_gamma = (const float*)d_in[8];
    const float* bn_beta  = (const float*)d_in[9];
    const float* bn_mean  = (const float*)d_in[10];
    const float* bn_var   = (const float*)d_in[11];
    const float* out_W1   = (const float*)d_in[12];
    const float* out_b1   = (const float*)d_in[13];
    const float* out_W2   = (const float*)d_in[14];
    const float* out_b2   = (const float*)d_in[15];
    const float* fc1_W    = (const float*)d_in[16];
    const float* fc1_b    = (const float*)d_in[17];
    const float* fc2_W    = (const float*)d_in[18];
    const float* fc2_b    = (const float*)d_in[19];
    float* out = (float*)d_out;

    const int* src = edge;
    const int* dst = edge + NE;

    float *p_x, *p_y, *p_h;
    cudaGetSymbolAddress((void**)&p_x, g_x);
    cudaGetSymbolAddress((void**)&p_y, g_y);
    cudaGetSymbolAddress((void**)&p_h, g_h);

    cudaFuncSetAttribute(k_gemm_tc<0>, cudaFuncAttributeMaxDynamicSharedMemorySize, SM_REQ);
    cudaFuncSetAttribute(k_gemm_tc<1>, cudaFuncAttributeMaxDynamicSharedMemorySize, SM_REQ);

    // CSR build (once per replay)
    k_zero_deg<<<(NN + 255) / 256, 256>>>();
    k_hist<<<(NE + 255) / 256, 256>>>(dst);
    k_scan<<<1, 1024>>>();
    k_csr<<<(NE + 255) / 256, 256>>>(src, dst);

    // embedding
    k_embed<<<(NN * 32 + 255) / 256, 256>>>(node_ids, emb);

    const int GB = (NN + 127) / 128;  // 391 gemm blocks

    for (int L = 0; L < 6; L++) {
        k_agg<<<(NN * 32 + 255) / 256, 256>>>();
        const float* W1 = (L < 5) ? in_W1 : out_W1;
        const float* b1 = (L < 5) ? in_b1 : out_b1;
        const float* W2 = (L < 5) ? in_W2 : out_W2;
        const float* b2 = (L < 5) ? in_b2 : out_b2;
        k_gemm_tc<0><<<GB, 256, SM_REQ>>>(p_y, W1, b1, nullptr, nullptr, nullptr, nullptr, p_h);
        if (L < 5)
            k_gemm_tc<1><<<GB, 256, SM_REQ>>>(p_h, W2, b2, bn_gamma, bn_beta, bn_mean, bn_var, p_x);
        else
            k_gemm_tc<0><<<GB, 256, SM_REQ>>>(p_h, W2, b2, nullptr, nullptr, nullptr, nullptr, p_x);
    }

    // pooling + FC head
    k_zero_pool<<<(NG * SD + 255) / 256, 256>>>();
    k_pool<<<(NN + NODES_PB - 1) / NODES_PB, 128>>>(batch);
    k_fc<<<NG, 128>>>(fc1_W, fc1_b, fc2_W, fc2_b, out);
}

// round 4
// speedup vs baseline: 1.1948x; 1.1948x over previous
#include <cuda_runtime.h>
#include <cstdint>

#define NN 50000
#define NE 800000
#define SD 128
#define NG 128
#define NC 41
#define BN_EPS 1e-5f

// ---------------- scratch (static device globals; no runtime alloc) -------
__device__ float g_x[NN * SD];
__device__ float g_y[NN * SD];
__device__ float g_h[NN * SD];
__device__ int   g_deg[NN];
__device__ int   g_rowptr[NN + 1];
__device__ int   g_cursor[NN];
__device__ int   g_csrsrc[NE];
__device__ float g_pool[NG * SD];

// fragment-permuted tf32 hi/lo weights: 4 matrices (in_W1,in_W2,out_W1,out_W2)
#define WPF 16384
__device__ float g_whi[4 * WPF];
__device__ float g_wlo[4 * WPF];

__device__ __forceinline__ float tf32_trunc(float v) {
    return __uint_as_float(__float_as_uint(v) & 0xffffe000u);
}

// ---------------- small utility kernels ----------------------------------
__global__ void k_zero_deg() {
    int i = blockIdx.x * blockDim.x + threadIdx.x;
    if (i < NN) g_deg[i] = 0;
}
__global__ void k_zero_pool() {
    int i = blockIdx.x * blockDim.x + threadIdx.x;
    if (i < NG * SD) g_pool[i] = 0.f;
}
__global__ void k_hist(const int* __restrict__ dst) {
    int e = blockIdx.x * blockDim.x + threadIdx.x;
    if (e < NE) atomicAdd(&g_deg[dst[e]], 1);
}
__global__ void k_scan() {
    __shared__ int wsum[32];
    int tid = threadIdx.x, lane = tid & 31, wid = tid >> 5;
    int base = 0;
    for (int c0 = 0; c0 < NN; c0 += 1024) {
        int i = c0 + tid;
        int v = (i < NN) ? g_deg[i] : 0;
        int s = v;
#pragma unroll
        for (int d = 1; d < 32; d <<= 1) {
            int t = __shfl_up_sync(0xffffffffu, s, d);
            if (lane >= d) s += t;
        }
        if (lane == 31) wsum[wid] = s;
        __syncthreads();
        if (wid == 0) {
            int t = wsum[lane];
#pragma unroll
            for (int d = 1; d < 32; d <<= 1) {
                int u = __shfl_up_sync(0xffffffffu, t, d);
                if (lane >= d) t += u;
            }
            wsum[lane] = t;
        }
        __syncthreads();
        int off = base + (wid ? wsum[wid - 1] : 0) + s - v;
        if (i < NN) { g_rowptr[i] = off; g_cursor[i] = off; }
        base += wsum[31];
        __syncthreads();
    }
    if (tid == 0) g_rowptr[NN] = base;
}
__global__ void k_csr(const int* __restrict__ src, const int* __restrict__ dst) {
    int e = blockIdx.x * blockDim.x + threadIdx.x;
    if (e < NE) {
        int p = atomicAdd(&g_cursor[dst[e]], 1);
        g_csrsrc[p] = src[e];
    }
}
__global__ void k_embed(const int* __restrict__ ids, const float* __restrict__ emb) {
    int t = blockIdx.x * blockDim.x + threadIdx.x;
    if (t >= NN * 32) return;
    int n = t >> 5, q = t & 31;
    ((float4*)g_x)[n * 32 + q] = ((const float4*)emb)[(long)ids[n] * 32 + q];
}

// warp-per-node: y[i] = x[i] + sum_{j in N(i)} x[j]
__global__ void k_agg() {
    int w = (blockIdx.x * blockDim.x + threadIdx.x) >> 5;
    int lane = threadIdx.x & 31;
    if (w >= NN) return;
    const float4* x4 = (const float4*)g_x;
    float4 a = x4[w * 32 + lane];
    int e = g_rowptr[w], end = g_rowptr[w + 1];
    for (; e + 2 <= end; e += 2) {
        int j0 = g_csrsrc[e], j1 = g_csrsrc[e + 1];
        float4 v0 = x4[j0 * 32 + lane];
        float4 v1 = x4[j1 * 32 + lane];
        a.x += v0.x + v1.x; a.y += v0.y + v1.y;
        a.z += v0.z + v1.z; a.w += v0.w + v1.w;
    }
    if (e < end) {
        int j = g_csrsrc[e];
        float4 v = x4[j * 32 + lane];
        a.x += v.x; a.y += v.y; a.z += v.z; a.w += v.w;
    }
    ((float4*)g_y)[w * 32 + lane] = a;
}

// ---------------- W split+permute precompute (once per replay) ------------
// element (n,k) -> fragment-permuted slot; two floats (k&7<4 / >=4) per lane.
__global__ void k_wsplit(const float* __restrict__ W, float* __restrict__ hi,
                         float* __restrict__ lo) {
    int t = blockIdx.x * blockDim.x + threadIdx.x;
    if (t >= 128 * 128) return;
    int n = t >> 7, k = t & 127;
    float v = W[n * 128 + k];
    float h = tf32_trunc(v);
    float l = tf32_trunc(v - h);
    int idx = (((k >> 3) * 16 + (n >> 3)) * 32 + ((n & 7) * 4 + (k & 3))) * 2 + ((k & 7) >> 2);
    hi[idx] = h;
    lo[idx] = l;
}

// ---------------- tensor-core GEMM via mma.sync (3xTF32, no SMEM) ----------
__device__ __forceinline__ void mma1688(float* c, const float4& a, const float2& b) {
    const uint32_t* A = reinterpret_cast<const uint32_t*>(&a);
    const uint32_t* B = reinterpret_cast<const uint32_t*>(&b);
    asm volatile(
        "mma.sync.aligned.m16n8k8.row.col.f32.tf32.tf32.f32 "
        "{%0,%1,%2,%3}, {%4,%5,%6,%7}, {%8,%9}, {%0,%1,%2,%3};"
        : "+f"(c[0]), "+f"(c[1]), "+f"(c[2]), "+f"(c[3])
        : "r"(A[0]), "r"(A[1]), "r"(A[2]), "r"(A[3]), "r"(B[0]), "r"(B[1]));
}

template <int BN_MODE>
__global__ void __launch_bounds__(256) k_gemm_tc(
    const float* __restrict__ A,
    const float* __restrict__ Whi, const float* __restrict__ Wlo,
    const float* __restrict__ bias,
    const float* __restrict__ gamma, const float* __restrict__ beta,
    const float* __restrict__ mean, const float* __restrict__ var,
    float* __restrict__ C)
{
    const int tid  = threadIdx.x;
    const int lane = tid & 31;
    const int wid  = tid >> 5;
    const int r0   = blockIdx.x * 128;
    const int wm   = (wid & 3) * 32;   // warp row offset
    const int wn   = (wid >> 2) * 64;  // warp col offset
    const int nt0  = wn >> 3;          // first n-tile index

    // A fragment base pointers (2 m-tiles x 2 row-halves), rows clamped
    const float* pa0[2];
    const float* pa1[2];
#pragma unroll
    for (int m = 0; m < 2; m++) {
        int R  = wm + m * 16 + (lane >> 2);
        int g0 = r0 + R;      if (g0 > NN - 1) g0 = NN - 1;
        int g1 = r0 + R + 8;  if (g1 > NN - 1) g1 = NN - 1;
        pa0[m] = A + (long)g0 * 128 + (lane & 3);
        pa1[m] = A + (long)g1 * 128 + (lane & 3);
    }
    const float2* wh2 = (const float2*)Whi + (long)nt0 * 32 + lane;
    const float2* wl2 = (const float2*)Wlo + (long)nt0 * 32 + lane;

    float acc[2][8][4];
#pragma unroll
    for (int m = 0; m < 2; m++)
#pragma unroll
        for (int n = 0; n < 8; n++)
#pragma unroll
            for (int j = 0; j < 4; j++) acc[m][n][j] = 0.f;

#pragma unroll 4
    for (int gk = 0; gk < 16; gk++) {
        int ko = gk * 8;
        float4 ah[2], al[2];
#pragma unroll
        for (int m = 0; m < 2; m++) {
            float4 v;
            v.x = __ldcg(pa0[m] + ko);
            v.y = __ldcg(pa1[m] + ko);
            v.z = __ldcg(pa0[m] + ko + 4);
            v.w = __ldcg(pa1[m] + ko + 4);
            ah[m].x = tf32_trunc(v.x); al[m].x = tf32_trunc(v.x - ah[m].x);
            ah[m].y = tf32_trunc(v.y); al[m].y = tf32_trunc(v.y - ah[m].y);
            ah[m].z = tf32_trunc(v.z); al[m].z = tf32_trunc(v.z - ah[m].z);
            ah[m].w = tf32_trunc(v.w); al[m].w = tf32_trunc(v.w - ah[m].w);
        }
        const float2* whk = wh2 + (long)gk * 16 * 32;
        const float2* wlk = wl2 + (long)gk * 16 * 32;
#pragma unroll
        for (int n = 0; n < 8; n++) {
            float2 wh = __ldg(whk + n * 32);
            float2 wl = __ldg(wlk + n * 32);
#pragma unroll
            for (int m = 0; m < 2; m++) {
                mma1688(acc[m][n], ah[m], wh);
                mma1688(acc[m][n], ah[m], wl);
                mma1688(acc[m][n], al[m], wh);
            }
        }
    }

    // ---- epilogue: bias/relu/(bn), float2 stores ----
#pragma unroll
    for (int m = 0; m < 2; m++) {
        int rbase = r0 + wm + m * 16 + (lane >> 2);
#pragma unroll
        for (int n = 0; n < 8; n++) {
            int col = wn + n * 8 + (lane & 3) * 2;
            float b0 = __ldg(&bias[col]), b1 = __ldg(&bias[col + 1]);
            float sc0 = 0.f, sc1 = 0.f, mn0 = 0.f, mn1 = 0.f, bt0 = 0.f, bt1 = 0.f;
            if (BN_MODE) {
                sc0 = __ldg(&gamma[col]) * rsqrtf(__ldg(&var[col]) + BN_EPS);
                sc1 = __ldg(&gamma[col + 1]) * rsqrtf(__ldg(&var[col + 1]) + BN_EPS);
                mn0 = __ldg(&mean[col]); mn1 = __ldg(&mean[col + 1]);
                bt0 = __ldg(&beta[col]); bt1 = __ldg(&beta[col + 1]);
            }
#pragma unroll
            for (int h = 0; h < 2; h++) {
                int r = rbase + h * 8;
                if (r < NN) {
                    float z0 = fmaxf(acc[m][n][h * 2 + 0] + b0, 0.f);
                    float z1 = fmaxf(acc[m][n][h * 2 + 1] + b1, 0.f);
                    if (BN_MODE) {
                        z0 = (z0 - mn0) * sc0 + bt0;
                        z1 = (z1 - mn1) * sc1 + bt1;
                    }
                    *(float2*)(C + (long)r * 128 + col) = make_float2(z0, z1);
                }
            }
        }
    }
}

// ---------------- pooling (batch is sorted -> run-length accumulate) ------
#define NODES_PB 250
__global__ void k_pool(const int* __restrict__ batch) {
    int c = threadIdx.x;
    int n0 = blockIdx.x * NODES_PB;
    int n1 = n0 + NODES_PB;
    if (n1 > NN) n1 = NN;
    if (n0 >= NN) return;
    float acc = 0.f;
    int cur = batch[n0];
    for (int n = n0; n < n1; n++) {
        int b = __ldg(&batch[n]);
        float v = g_x[(long)n * SD + c];
        if (b != cur) {
            atomicAdd(&g_pool[cur * SD + c], acc);
            acc = 0.f; cur = b;
        }
        acc += v;
    }
    atomicAdd(&g_pool[cur * SD + c], acc);
}

// ---------------- tiny FC head: one block per graph -----------------------
__global__ void k_fc(const float* __restrict__ fc1W, const float* __restrict__ fc1b,
                     const float* __restrict__ fc2W, const float* __restrict__ fc2b,
                     float* __restrict__ out) {
    __shared__ float p[SD];
    __shared__ float h[SD];
    int g = blockIdx.x, t = threadIdx.x;
    p[t] = g_pool[g * SD + t];
    __syncthreads();
    float s = fc1b[t];
#pragma unroll 8
    for (int k = 0; k < SD; k++) s += p[k] * fc1W[t * SD + k];
    h[t] = fmaxf(s, 0.f);
    __syncthreads();
    if (t < NC) {
        float s2 = fc2b[t];
#pragma unroll 8
        for (int k = 0; k < SD; k++) s2 += h[k] * fc2W[t * SD + k];
        out[g * NC + t] = s2;
    }
}

// ---------------- launch ---------------------------------------------------
extern "C" void kernel_launch(void* const* d_in, const int* in_sizes, int n_in,
                              void* d_out, int out_size) {
    const int*   node_ids = (const int*)d_in[0];
    const int*   edge     = (const int*)d_in[1];
    const int*   batch    = (const int*)d_in[2];
    const float* emb      = (const float*)d_in[3];
    const float* in_W1    = (const float*)d_in[4];
    const float* in_b1    = (const float*)d_in[5];
    const float* in_W2    = (const float*)d_in[6];
    const float* in_b2    = (const float*)d_in[7];
    const float* bn_gamma = (const float*)d_in[8];
    const float* bn_beta  = (const float*)d_in[9];
    const float* bn_mean  = (const float*)d_in[10];
    const float* bn_var   = (const float*)d_in[11];
    const float* out_W1   = (const float*)d_in[12];
    const float* out_b1   = (const float*)d_in[13];
    const float* out_W2   = (const float*)d_in[14];
    const float* out_b2   = (const float*)d_in[15];
    const float* fc1_W    = (const float*)d_in[16];
    const float* fc1_b    = (const float*)d_in[17];
    const float* fc2_W    = (const float*)d_in[18];
    const float* fc2_b    = (const float*)d_in[19];
    float* out = (float*)d_out;

    const int* src = edge;
    const int* dst = edge + NE;

    float *p_x, *p_y, *p_h, *p_whi, *p_wlo;
    cudaGetSymbolAddress((void**)&p_x, g_x);
    cudaGetSymbolAddress((void**)&p_y, g_y);
    cudaGetSymbolAddress((void**)&p_h, g_h);
    cudaGetSymbolAddress((void**)&p_whi, g_whi);
    cudaGetSymbolAddress((void**)&p_wlo, g_wlo);

    // W split+permute (4 matrices, once per replay)
    const float* Ws[4] = {in_W1, in_W2, out_W1, out_W2};
    for (int i = 0; i < 4; i++)
        k_wsplit<<<64, 256>>>(Ws[i], p_whi + i * WPF, p_wlo + i * WPF);

    // CSR build (once per replay)
    k_zero_deg<<<(NN + 255) / 256, 256>>>();
    k_hist<<<(NE + 255) / 256, 256>>>(dst);
    k_scan<<<1, 1024>>>();
    k_csr<<<(NE + 255) / 256, 256>>>(src, dst);

    // embedding
    k_embed<<<(NN * 32 + 255) / 256, 256>>>(node_ids, emb);

    const int GB = (NN + 127) / 128;  // 391 gemm blocks

    for (int L = 0; L < 6; L++) {
        k_agg<<<(NN * 32 + 255) / 256, 256>>>();
        int w1 = (L < 5) ? 0 : 2, w2 = (L < 5) ? 1 : 3;
        const float* b1 = (L < 5) ? in_b1 : out_b1;
        const float* b2 = (L < 5) ? in_b2 : out_b2;
        k_gemm_tc<0><<<GB, 256>>>(p_y, p_whi + w1 * WPF, p_wlo + w1 * WPF, b1,
                                  nullptr, nullptr, nullptr, nullptr, p_h);
        if (L < 5)
            k_gemm_tc<1><<<GB, 256>>>(p_h, p_whi + w2 * WPF, p_wlo + w2 * WPF, b2,
                                      bn_gamma, bn_beta, bn_mean, bn_var, p_x);
        else
            k_gemm_tc<0><<<GB, 256>>>(p_h, p_whi + w2 * WPF, p_wlo + w2 * WPF, b2,
                                      nullptr, nullptr, nullptr, nullptr, p_x);
    }

    // pooling + FC head
    k_zero_pool<<<(NG * SD + 255) / 256, 256>>>();
    k_pool<<<(NN + NODES_PB - 1) / NODES_PB, 128>>>(batch);
    k_fc<<<NG, 128>>>(fc1_W, fc1_b, fc2_W, fc2_b, out);
}

// round 6
// speedup vs baseline: 1.6483x; 1.3796x over previous
#include <cuda_runtime.h>
#include <cstdint>

#define NN 50000
#define NE 800000
#define SD 128
#define NG 128
#define NC 41
#define BN_EPS 1e-5f

typedef unsigned int u32;
typedef unsigned short u16;

// ---------------- scratch (static device globals; no runtime alloc) -------
__device__ u32   g_xa[NN * SD];       // packed (bf16hi | bf16lo<<16) per element
__device__ u32   g_xb[NN * SD];       // double buffer
__device__ int   g_deg[NN];
__device__ int   g_rowptr[NN + 1];
__device__ int   g_cursor[NN];
__device__ int   g_csrsrc[NE];
__device__ float g_pool[NG * SD];

// fragment-permuted bf16 hi/lo W fragments: 4 matrices, 8192 u32 words each
#define WFW 8192
__device__ __align__(16) u32 g_wfhi[4 * WFW];
__device__ __align__(16) u32 g_wflo[4 * WFW];

// ---------------- bf16 split helpers --------------------------------------
__device__ __forceinline__ u32 f2bf(float f) {          // RN-even, returns 16-bit
    u32 u = __float_as_uint(f);
    return (u + 0x7fffu + ((u >> 16) & 1u)) >> 16;
}
__device__ __forceinline__ u32 packsplit(float v) {
    u32 h = f2bf(v);
    float hv = __uint_as_float(h << 16);
    u32 l = f2bf(v - hv);
    return h | (l << 16);
}
__device__ __forceinline__ float unpack(u32 p) {
    return __uint_as_float(p << 16) + __uint_as_float(p & 0xffff0000u);
}
__device__ __forceinline__ u32 prmt(u32 a, u32 b, u32 s) {
    u32 d; asm("prmt.b32 %0,%1,%2,%3;" : "=r"(d) : "r"(a), "r"(b), "r"(s)); return d;
}

__device__ __forceinline__ void mma16816(float* c, const u32* a, const u32* b) {
    asm volatile(
        "mma.sync.aligned.m16n8k16.row.col.f32.bf16.bf16.f32 "
        "{%0,%1,%2,%3}, {%4,%5,%6,%7}, {%8,%9}, {%0,%1,%2,%3};"
        : "+f"(c[0]), "+f"(c[1]), "+f"(c[2]), "+f"(c[3])
        : "r"(a[0]), "r"(a[1]), "r"(a[2]), "r"(a[3]), "r"(b[0]), "r"(b[1]));
}

// ---------------- small utility kernels ----------------------------------
__global__ void k_zero_deg() {
    int i = blockIdx.x * blockDim.x + threadIdx.x;
    if (i < NN) g_deg[i] = 0;
}
__global__ void k_zero_pool() {
    int i = blockIdx.x * blockDim.x + threadIdx.x;
    if (i < NG * SD) g_pool[i] = 0.f;
}
__global__ void k_hist(const int* __restrict__ dst) {
    int e = blockIdx.x * blockDim.x + threadIdx.x;
    if (e < NE) atomicAdd(&g_deg[dst[e]], 1);
}
__global__ void k_scan() {
    __shared__ int wsum[32];
    int tid = threadIdx.x, lane = tid & 31, wid = tid >> 5;
    int base = 0;
    for (int c0 = 0; c0 < NN; c0 += 1024) {
        int i = c0 + tid;
        int v = (i < NN) ? g_deg[i] : 0;
        int s = v;
#pragma unroll
        for (int d = 1; d < 32; d <<= 1) {
            int t = __shfl_up_sync(0xffffffffu, s, d);
            if (lane >= d) s += t;
        }
        if (lane == 31) wsum[wid] = s;
        __syncthreads();
        if (wid == 0) {
            int t = wsum[lane];
#pragma unroll
            for (int d = 1; d < 32; d <<= 1) {
                int u = __shfl_up_sync(0xffffffffu, t, d);
                if (lane >= d) t += u;
            }
            wsum[lane] = t;
        }
        __syncthreads();
        int off = base + (wid ? wsum[wid - 1] : 0) + s - v;
        if (i < NN) { g_rowptr[i] = off; g_cursor[i] = off; }
        base += wsum[31];
        __syncthreads();
    }
    if (tid == 0) g_rowptr[NN] = base;
}
__global__ void k_csr(const int* __restrict__ src, const int* __restrict__ dst) {
    int e = blockIdx.x * blockDim.x + threadIdx.x;
    if (e < NE) {
        int p = atomicAdd(&g_cursor[dst[e]], 1);
        g_csrsrc[p] = src[e];
    }
}
__global__ void k_embed(const int* __restrict__ ids, const float* __restrict__ emb) {
    int t = blockIdx.x * blockDim.x + threadIdx.x;
    if (t >= NN * 32) return;
    int n = t >> 5, q = t & 31;
    float4 v = ((const float4*)emb)[(long)ids[n] * 32 + q];
    uint4 p;
    p.x = packsplit(v.x); p.y = packsplit(v.y);
    p.z = packsplit(v.z); p.w = packsplit(v.w);
    ((uint4*)g_xa)[n * 32 + q] = p;
}

// ---------------- W split into bf16 hi/lo mma-fragment layout --------------
__global__ void k_wsplit(const float* __restrict__ W, u16* __restrict__ hi,
                         u16* __restrict__ lo) {
    int t = blockIdx.x * blockDim.x + threadIdx.x;
    if (t >= 128 * 128) return;
    int n = t >> 7, k = t & 127;
    float v = W[n * 128 + k];
    u32 h = f2bf(v);
    u32 l = f2bf(v - __uint_as_float(h << 16));
    int ks = k >> 4, nt = n >> 3, kl = k & 15;
    int lane = ((n & 7) << 2) | ((kl >> 1) & 3);
    int widx = ((ks * 16 + nt) * 32 + lane) * 2 + (kl >> 3);
    hi[widx * 2 + (kl & 1)] = (u16)h;
    lo[widx * 2 + (kl & 1)] = (u16)l;
}

// ---------------- fused layer kernel ---------------------------------------
__device__ __forceinline__ void gemm_pass(
    const u32* sA, const u32* wfhi, const u32* wflo,
    int wm, int wn, int lane, float acc[2][8][4])
{
#pragma unroll
    for (int m = 0; m < 2; m++)
#pragma unroll
        for (int n = 0; n < 8; n++)
#pragma unroll
            for (int j = 0; j < 4; j++) acc[m][n][j] = 0.f;

#pragma unroll
    for (int ks = 0; ks < 8; ks++) {
        u32 ah[2][4], al[2][4];
#pragma unroll
        for (int m = 0; m < 2; m++) {
            int row0 = wm + m * 16 + (lane >> 2);
            int row1 = row0 + 8;
            int kp0 = ks * 8 + (lane & 3);
            int kp1 = kp0 + 4;
            int g00 = row0 * 64 + (kp0 ^ ((row0 & 7) << 2));
            int g10 = row1 * 64 + (kp0 ^ ((row1 & 7) << 2));
            int g01 = row0 * 64 + (kp1 ^ ((row0 & 7) << 2));
            int g11 = row1 * 64 + (kp1 ^ ((row1 & 7) << 2));
            uint2 p00 = *(const uint2*)(sA + g00 * 2);
            uint2 p10 = *(const uint2*)(sA + g10 * 2);
            uint2 p01 = *(const uint2*)(sA + g01 * 2);
            uint2 p11 = *(const uint2*)(sA + g11 * 2);
            ah[m][0] = prmt(p00.x, p00.y, 0x5410); al[m][0] = prmt(p00.x, p00.y, 0x7632);
            ah[m][1] = prmt(p10.x, p10.y, 0x5410); al[m][1] = prmt(p10.x, p10.y, 0x7632);
            ah[m][2] = prmt(p01.x, p01.y, 0x5410); al[m][2] = prmt(p01.x, p01.y, 0x7632);
            ah[m][3] = prmt(p11.x, p11.y, 0x5410); al[m][3] = prmt(p11.x, p11.y, 0x7632);
        }
#pragma unroll
        for (int n = 0; n < 8; n++) {
            int nt = (wn >> 3) + n;
            uint2 bh = __ldg((const uint2*)wfhi + (ks * 16 + nt) * 32 + lane);
            uint2 bl = __ldg((const uint2*)wflo + (ks * 16 + nt) * 32 + lane);
#pragma unroll
            for (int m = 0; m < 2; m++) {
                mma16816(acc[m][n], ah[m], (const u32*)&bh);
                mma16816(acc[m][n], ah[m], (const u32*)&bl);
                mma16816(acc[m][n], al[m], (const u32*)&bh);
            }
        }
    }
}

template <int BN_MODE>
__global__ void __launch_bounds__(256, 2) k_layer(
    const u32* __restrict__ X, u32* __restrict__ Xout,
    const u32* __restrict__ w1hi, const u32* __restrict__ w1lo,
    const float* __restrict__ b1,
    const u32* __restrict__ w2hi, const u32* __restrict__ w2lo,
    const float* __restrict__ b2,
    const float* __restrict__ gamma, const float* __restrict__ beta,
    const float* __restrict__ mean, const float* __restrict__ var)
{
    extern __shared__ __align__(16) u32 sA[];   // 128 * 64 * 2 u32 = 64KB
    const int tid  = threadIdx.x;
    const int lane = tid & 31;
    const int wid  = tid >> 5;
    const int r0   = blockIdx.x * 128;
    const int wm   = (wid & 3) * 32;
    const int wn   = (wid >> 2) * 64;

    // ---- Phase A: aggregation y = x_self + sum_neigh, into SMEM ----
    const uint4* x4 = (const uint4*)X;
#pragma unroll 1
    for (int t = 0; t < 16; t++) {
        int nd = r0 + wid * 16 + t;
        if (nd >= NN) break;
        uint4 sv = x4[(long)nd * 32 + lane];
        float s0 = unpack(sv.x), s1 = unpack(sv.y), s2 = unpack(sv.z), s3 = unpack(sv.w);
        int e = g_rowptr[nd], end = g_rowptr[nd + 1];
        for (; e + 2 <= end; e += 2) {
            int j0 = g_csrsrc[e], j1 = g_csrsrc[e + 1];
            uint4 v0 = __ldg(x4 + (long)j0 * 32 + lane);
            uint4 v1 = __ldg(x4 + (long)j1 * 32 + lane);
            s0 += unpack(v0.x) + unpack(v1.x);
            s1 += unpack(v0.y) + unpack(v1.y);
            s2 += unpack(v0.z) + unpack(v1.z);
            s3 += unpack(v0.w) + unpack(v1.w);
        }
        if (e < end) {
            uint4 v = __ldg(x4 + (long)g_csrsrc[e] * 32 + lane);
            s0 += unpack(v.x); s1 += unpack(v.y); s2 += unpack(v.z); s3 += unpack(v.w);
        }
        int row = nd - r0;
        int g = row * 64 + ((lane * 2) ^ ((row & 7) << 2));
        uint4 o;
        o.x = packsplit(s0); o.y = packsplit(s1);
        o.z = packsplit(s2); o.w = packsplit(s3);
        *(uint4*)(sA + g * 2) = o;
    }
    __syncthreads();

    // ---- Phase B: h = relu(y@W1 + b1), re-split into SMEM ----
    float acc[2][8][4];
    gemm_pass(sA, w1hi, w1lo, wm, wn, lane, acc);
    __syncthreads();
#pragma unroll
    for (int m = 0; m < 2; m++) {
        int row0 = wm + m * 16 + (lane >> 2);
        int row1 = row0 + 8;
#pragma unroll
        for (int n = 0; n < 8; n++) {
            int col = wn + n * 8 + (lane & 3) * 2;
            float bb0 = __ldg(&b1[col]), bb1 = __ldg(&b1[col + 1]);
            float v0 = fmaxf(acc[m][n][0] + bb0, 0.f);
            float v1 = fmaxf(acc[m][n][1] + bb1, 0.f);
            float v2 = fmaxf(acc[m][n][2] + bb0, 0.f);
            float v3 = fmaxf(acc[m][n][3] + bb1, 0.f);
            int kp = col >> 1;
            int g0 = row0 * 64 + (kp ^ ((row0 & 7) << 2));
            int g1 = row1 * 64 + (kp ^ ((row1 & 7) << 2));
            *(uint2*)(sA + g0 * 2) = make_uint2(packsplit(v0), packsplit(v1));
            *(uint2*)(sA + g1 * 2) = make_uint2(packsplit(v2), packsplit(v3));
        }
    }
    __syncthreads();

    // ---- Phase C: x = [bn](relu(h@W2 + b2)) -> global packed ----
    gemm_pass(sA, w2hi, w2lo, wm, wn, lane, acc);
#pragma unroll
    for (int m = 0; m < 2; m++) {
        int row0 = wm + m * 16 + (lane >> 2);
#pragma unroll
        for (int n = 0; n < 8; n++) {
            int col = wn + n * 8 + (lane & 3) * 2;
            float bb0 = __ldg(&b2[col]), bb1 = __ldg(&b2[col + 1]);
            float sc0 = 0.f, sc1 = 0.f, mn0 = 0.f, mn1 = 0.f, bt0 = 0.f, bt1 = 0.f;
            if (BN_MODE) {
                sc0 = __ldg(&gamma[col]) * rsqrtf(__ldg(&var[col]) + BN_EPS);
                sc1 = __ldg(&gamma[col + 1]) * rsqrtf(__ldg(&var[col + 1]) + BN_EPS);
                mn0 = __ldg(&mean[col]); mn1 = __ldg(&mean[col + 1]);
                bt0 = __ldg(&beta[col]); bt1 = __ldg(&beta[col + 1]);
            }
#pragma unroll
            for (int h = 0; h < 2; h++) {
                int r = r0 + row0 + h * 8;
                if (r < NN) {
                    float z0 = fmaxf(acc[m][n][h * 2 + 0] + bb0, 0.f);
                    float z1 = fmaxf(acc[m][n][h * 2 + 1] + bb1, 0.f);
                    if (BN_MODE) {
                        z0 = (z0 - mn0) * sc0 + bt0;
                        z1 = (z1 - mn1) * sc1 + bt1;
                    }
                    *(uint2*)(Xout + (long)r * 128 + col) =
                        make_uint2(packsplit(z0), packsplit(z1));
                }
            }
        }
    }
}

// ---------------- pooling (batch sorted -> run-length accumulate) ----------
#define NODES_PB 250
__global__ void k_pool(const u32* __restrict__ X, const int* __restrict__ batch) {
    int c = threadIdx.x;
    int n0 = blockIdx.x * NODES_PB;
    int n1 = n0 + NODES_PB;
    if (n1 > NN) n1 = NN;
    if (n0 >= NN) return;
    float acc = 0.f;
    int cur = batch[n0];
    for (int n = n0; n < n1; n++) {
        int b = __ldg(&batch[n]);
        float v = unpack(X[(long)n * SD + c]);
        if (b != cur) {
            atomicAdd(&g_pool[cur * SD + c], acc);
            acc = 0.f; cur = b;
        }
        acc += v;
    }
    atomicAdd(&g_pool[cur * SD + c], acc);
}

// ---------------- tiny FC head: one block per graph -----------------------
__global__ void k_fc(const float* __restrict__ fc1W, const float* __restrict__ fc1b,
                     const float* __restrict__ fc2W, const float* __restrict__ fc2b,
                     float* __restrict__ out) {
    __shared__ float p[SD];
    __shared__ float h[SD];
    int g = blockIdx.x, t = threadIdx.x;
    p[t] = g_pool[g * SD + t];
    __syncthreads();
    float s = fc1b[t];
#pragma unroll 8
    for (int k = 0; k < SD; k++) s += p[k] * fc1W[t * SD + k];
    h[t] = fmaxf(s, 0.f);
    __syncthreads();
    if (t < NC) {
        float s2 = fc2b[t];
#pragma unroll 8
        for (int k = 0; k < SD; k++) s2 += h[k] * fc2W[t * SD + k];
        out[g * NC + t] = s2;
    }
}

// ---------------- launch ---------------------------------------------------
#define SM_LAYER (128 * 64 * 8)

extern "C" void kernel_launch(void* const* d_in, const int* in_sizes, int n_in,
                              void* d_out, int out_size) {
    const int*   node_ids = (const int*)d_in[0];
    const int*   edge     = (const int*)d_in[1];
    const int*   batch    = (const int*)d_in[2];
    const float* emb      = (const float*)d_in[3];
    const float* in_W1    = (const float*)d_in[4];
    const float* in_b1    = (const float*)d_in[5];
    const float* in_W2    = (const float*)d_in[6];
    const float* in_b2    = (const float*)d_in[7];
    const float* bn_gamma = (const float*)d_in[8];
    const float* bn_beta  = (const float*)d_in[9];
    const float* bn_mean  = (const float*)d_in[10];
    const float* bn_var   = (const float*)d_in[11];
    const float* out_W1   = (const float*)d_in[12];
    const float* out_b1   = (const float*)d_in[13];
    const float* out_W2   = (const float*)d_in[14];
    const float* out_b2   = (const float*)d_in[15];
    const float* fc1_W    = (const float*)d_in[16];
    const float* fc1_b    = (const float*)d_in[17];
    const float* fc2_W    = (const float*)d_in[18];
    const float* fc2_b    = (const float*)d_in[19];
    float* out = (float*)d_out;

    const int* src = edge;
    const int* dst = edge + NE;

    u32 *p_xa, *p_xb, *p_whi, *p_wlo;
    cudaGetSymbolAddress((void**)&p_xa, g_xa);
    cudaGetSymbolAddress((void**)&p_xb, g_xb);
    cudaGetSymbolAddress((void**)&p_whi, g_wfhi);
    cudaGetSymbolAddress((void**)&p_wlo, g_wflo);

    cudaFuncSetAttribute(k_layer<0>, cudaFuncAttributeMaxDynamicSharedMemorySize, SM_LAYER);
    cudaFuncSetAttribute(k_layer<1>, cudaFuncAttributeMaxDynamicSharedMemorySize, SM_LAYER);

    // W fragment precompute (4 matrices, once per replay)
    const float* Ws[4] = {in_W1, in_W2, out_W1, out_W2};
    for (int i = 0; i < 4; i++)
        k_wsplit<<<64, 256>>>(Ws[i], (u16*)(p_whi + i * WFW), (u16*)(p_wlo + i * WFW));

    // CSR build (once per replay)
    k_zero_deg<<<(NN + 255) / 256, 256>>>();
    k_hist<<<(NE + 255) / 256, 256>>>(dst);
    k_scan<<<1, 1024>>>();
    k_csr<<<(NE + 255) / 256, 256>>>(src, dst);

    // embedding -> packed x (into buffer A)
    k_embed<<<(NN * 32 + 255) / 256, 256>>>(node_ids, emb);

    const int GB = (NN + 127) / 128;  // 391 blocks

    u32* cur = p_xa;
    u32* nxt = p_xb;
    for (int L = 0; L < 6; L++) {
        int w1 = (L < 5) ? 0 : 2, w2 = (L < 5) ? 1 : 3;
        const float* b1 = (L < 5) ? in_b1 : out_b1;
        const float* b2 = (L < 5) ? in_b2 : out_b2;
        if (L < 5)
            k_layer<1><<<GB, 256, SM_LAYER>>>(cur, nxt,
                p_whi + w1 * WFW, p_wlo + w1 * WFW, b1,
                p_whi + w2 * WFW, p_wlo + w2 * WFW, b2,
                bn_gamma, bn_beta, bn_mean, bn_var);
        else
            k_layer<0><<<GB, 256, SM_LAYER>>>(cur, nxt,
                p_whi + w1 * WFW, p_wlo + w1 * WFW, b1,
                p_whi + w2 * WFW, p_wlo + w2 * WFW, b2,
                nullptr, nullptr, nullptr, nullptr);
        u32* t = cur; cur = nxt; nxt = t;
    }
    // after 6 layers, result is in `cur` (== p_xa)

    // pooling + FC head
    k_zero_pool<<<(NG * SD + 255) / 256, 256>>>();
    k_pool<<<(NN + NODES_PB - 1) / NODES_PB, 128>>>(cur, batch);
    k_fc<<<NG, 128>>>(fc1_W, fc1_b, fc2_W, fc2_b, out);
}